// round 11
// baseline (speedup 1.0000x reference)
#include <cuda_runtime.h>
#include <cstdint>

#define BATCH   16
#define H       128
#define W       128
#define NC      80
#define ROWLEN  (W * NC)        // 10240
#define BATCHLEN (H * ROWLEN)   // 1310720
#define TOPK    100
#define NBINS   2048

// Scratch (device globals: allocation-free contract)
__device__ unsigned long long g_cand[BATCH][BATCHLEN];
__device__ unsigned int g_cnt[BATCH];
__device__ unsigned int g_hist[BATCH][NBINS];

// The ONE sigmoid (identical formula wherever p is produced).
__device__ __forceinline__ float sigmoidf_(float x) {
    return 1.0f / (1.0f + __expf(-x));
}

__global__ void zero_kernel() {
    unsigned i = blockIdx.x * blockDim.x + threadIdx.x;
    for (unsigned k = i; k < BATCH * NBINS; k += gridDim.x * blockDim.x)
        ((unsigned*)g_hist)[k] = 0u;
    if (i < BATCH) g_cnt[i] = 0u;
}

__device__ __forceinline__ float4 maxf4(float4 a, float4 b) {
    return make_float4(fmaxf(a.x, b.x), fmaxf(a.y, b.y),
                       fmaxf(a.z, b.z), fmaxf(a.w, b.w));
}

__device__ __forceinline__ unsigned sortable_(float v) {
    unsigned u = __float_as_uint(v);
    return ((int)u < 0) ? ~u : (u | 0x80000000u);
}

#define YSTRIP   32
#define NWARPS   8
#define WBUF     512
#define WFLUSH   (WBUF - 128)   // max 128 appended per row per warp

// Peak-NMS: logit-domain separable 3x3 max. Keys stored as
// (sortable_logit<<32 | ~idx) — NO sigmoid here. Warp-autonomous appends via
// 3 bit-plane ballots (per-lane count 0..4 -> prefix in one popc pass).
__global__ __launch_bounds__(256) void peak_kernel(const float* __restrict__ cls) {
    __shared__ unsigned long long sbuf[NWARPS][WBUF];

    const int tid  = threadIdx.x;
    const int wid  = tid >> 5;
    const int lane = tid & 31;
    const unsigned lane_lt = (1u << lane) - 1u;

    const int b  = blockIdx.z;
    const int ys = blockIdx.y;
    const int j  = blockIdx.x * 1024 + tid * 4;
    const int xc = j / NC;
    const bool hasL = (xc > 0);
    const bool hasR = (xc < W - 1);

    const float* base = cls + (size_t)b * BATCHLEN;
    const float NEG = __int_as_float(0xff800000);  // -inf
    const float4 NEG4 = make_float4(NEG, NEG, NEG, NEG);

    const int y0 = ys * YSTRIP;

    float4 hprev, hcur, vcur;
    if (y0 == 0) {
        hprev = NEG4;
    } else {
        const float* r = base + (y0 - 1) * ROWLEN + j;
        float4 Bv = *reinterpret_cast<const float4*>(r);
        float4 A = hasL ? *reinterpret_cast<const float4*>(r - NC) : NEG4;
        float4 C = hasR ? *reinterpret_cast<const float4*>(r + NC) : NEG4;
        hprev = maxf4(maxf4(A, Bv), C);
    }
    {
        const float* r = base + y0 * ROWLEN + j;
        float4 Bv = *reinterpret_cast<const float4*>(r);
        float4 A = hasL ? *reinterpret_cast<const float4*>(r - NC) : NEG4;
        float4 C = hasR ? *reinterpret_cast<const float4*>(r + NC) : NEG4;
        vcur = Bv;
        hcur = maxf4(maxf4(A, Bv), C);
    }

    unsigned wcnt = 0u;   // warp-uniform running count

    for (int y = y0; y < y0 + YSTRIP; ++y) {
        if (wcnt > (unsigned)WFLUSH) {
            __syncwarp();
            unsigned basep = 0u;
            if (lane == 0) basep = atomicAdd(&g_cnt[b], wcnt);
            basep = __shfl_sync(0xffffffffu, basep, 0);
            for (unsigned i = lane; i < wcnt; i += 32u)
                g_cand[b][basep + i] = sbuf[wid][i];
            wcnt = 0u;
        }

        float4 vnext, hnext;
        const int yn = y + 1;
        if (yn >= H) {
            vnext = NEG4; hnext = NEG4;
        } else {
            const float* r = base + yn * ROWLEN + j;
            float4 Bv = *reinterpret_cast<const float4*>(r);
            float4 A = hasL ? *reinterpret_cast<const float4*>(r - NC) : NEG4;
            float4 C = hasR ? *reinterpret_cast<const float4*>(r + NC) : NEG4;
            vnext = Bv;
            hnext = maxf4(maxf4(A, Bv), C);
        }

        float4 m = maxf4(maxf4(hprev, hcur), hnext);
        bool pk0 = (vcur.x == m.x);
        bool pk1 = (vcur.y == m.y);
        bool pk2 = (vcur.z == m.z);
        bool pk3 = (vcur.w == m.w);
        unsigned c = (unsigned)pk0 + (unsigned)pk1 + (unsigned)pk2 + (unsigned)pk3;

        unsigned B0 = __ballot_sync(0xffffffffu, c & 1u);
        unsigned B1 = __ballot_sync(0xffffffffu, c & 2u);
        unsigned B2 = __ballot_sync(0xffffffffu, c & 4u);
        unsigned prefix = __popc(B0 & lane_lt) + 2u * __popc(B1 & lane_lt)
                        + 4u * __popc(B2 & lane_lt);
        unsigned total  = __popc(B0) + 2u * __popc(B1) + 4u * __popc(B2);

        unsigned off = wcnt + prefix;
        const unsigned rowidx = (unsigned)(y * ROWLEN + j);

        if (pk0) {
            unsigned srt = sortable_(vcur.x);
            atomicAdd(&g_hist[b][srt >> 21], 1u);          // RED.GLOBAL
            sbuf[wid][off++] = ((unsigned long long)srt << 32)
                             | (unsigned long long)(0xFFFFFFFFu - (rowidx + 0u));
        }
        if (pk1) {
            unsigned srt = sortable_(vcur.y);
            atomicAdd(&g_hist[b][srt >> 21], 1u);
            sbuf[wid][off++] = ((unsigned long long)srt << 32)
                             | (unsigned long long)(0xFFFFFFFFu - (rowidx + 1u));
        }
        if (pk2) {
            unsigned srt = sortable_(vcur.z);
            atomicAdd(&g_hist[b][srt >> 21], 1u);
            sbuf[wid][off++] = ((unsigned long long)srt << 32)
                             | (unsigned long long)(0xFFFFFFFFu - (rowidx + 2u));
        }
        if (pk3) {
            unsigned srt = sortable_(vcur.w);
            atomicAdd(&g_hist[b][srt >> 21], 1u);
            sbuf[wid][off++] = ((unsigned long long)srt << 32)
                             | (unsigned long long)(0xFFFFFFFFu - (rowidx + 3u));
        }
        wcnt += total;

        hprev = hcur; hcur = hnext; vcur = vnext;
    }

    if (wcnt) {
        __syncwarp();
        unsigned basep = 0u;
        if (lane == 0) basep = atomicAdd(&g_cnt[b], wcnt);
        basep = __shfl_sync(0xffffffffu, basep, 0);
        for (unsigned i = lane; i < wcnt; i += 32u)
            g_cand[b][basep + i] = sbuf[wid][i];
    }
}

// Per-batch final: parallel suffix-scan over the 2048-bin logit histogram ->
// logit-domain threshold (one safety bucket lower), single collect scan,
// sigmoid on survivors, bitonic sort on (p_bits<<32 | ~idx) (exact jax ties).
__global__ __launch_bounds__(1024) void final_kernel(const float* __restrict__ dxy,
                                                     const float* __restrict__ swh,
                                                     float* __restrict__ out) {
    const int b = blockIdx.x;
    const int tid = threadIdx.x;
    const int bd = blockDim.x;   // 1024

    __shared__ unsigned int ssum[NBINS];          // suffix sums (reversed order)
    __shared__ unsigned long long list[4096];
    __shared__ unsigned int sh_thr;
    __shared__ unsigned int lcnt;

    unsigned N = g_cnt[b];
    if (N > (unsigned)BATCHLEN) N = BATCHLEN;
    const unsigned long long* cand = g_cand[b];

    // ssum[k] holds hist[2047-k]; inclusive prefix over k == suffix over bins
    ssum[tid]        = g_hist[b][NBINS - 1 - tid];
    ssum[tid + 1024] = g_hist[b][NBINS - 1 - (tid + 1024)];
    if (tid == 0) { lcnt = 0u; sh_thr = 0u; }
    __syncthreads();

    #pragma unroll
    for (unsigned ofs = 1u; ofs < (unsigned)NBINS; ofs <<= 1) {
        unsigned a0 = (tid >= ofs) ? ssum[tid - ofs] : 0u;
        unsigned k1 = tid + 1024u;
        unsigned a1 = (k1 >= ofs) ? ssum[k1 - ofs] : 0u;
        __syncthreads();
        ssum[tid] += a0;
        ssum[k1]  += a1;
        __syncthreads();
    }

    // kmin = smallest k with ssum[k] >= TOPK  -> bt = 2047 - kmin
    {
        unsigned k0 = tid, k1 = tid + 1024u;
        if (ssum[k0] >= (unsigned)TOPK && (k0 == 0u || ssum[k0 - 1u] < (unsigned)TOPK)) {
            int bt = NBINS - 1 - (int)k0;
            sh_thr = (unsigned)((bt >= 1) ? (bt - 1) : 0) << 21;
        }
        if (ssum[k1] >= (unsigned)TOPK && ssum[k1 - 1u] < (unsigned)TOPK) {
            int bt = NBINS - 1 - (int)k1;
            sh_thr = (unsigned)((bt >= 1) ? (bt - 1) : 0) << 21;
        }
    }
    __syncthreads();
    const unsigned T = sh_thr;   // sortable-logit threshold (0 => collect all)

    // single full pass over the candidate list
    for (unsigned i = tid; i < N; i += bd) {
        unsigned long long key = cand[i];
        if ((unsigned)(key >> 32) >= T) {
            unsigned p2 = atomicAdd(&lcnt, 1u);
            if (p2 < 4096u) list[p2] = key;
        }
    }
    __syncthreads();

    unsigned M = lcnt; if (M > 4096u) M = 4096u;

    // convert survivors: sortable logit -> p (identical sigmoid), key=(p,~idx)
    for (unsigned i = tid; i < M; i += bd) {
        unsigned long long key = list[i];
        unsigned srt = (unsigned)(key >> 32);
        unsigned bits = (srt & 0x80000000u) ? (srt ^ 0x80000000u) : ~srt;
        float p = sigmoidf_(__uint_as_float(bits));
        list[i] = ((unsigned long long)__float_as_uint(p) << 32)
                | (key & 0xFFFFFFFFull);
    }

    unsigned P = 128u;
    while (P < M) P <<= 1;
    __syncthreads();
    for (unsigned i = M + tid; i < P; i += bd) list[i] = 0ull;
    __syncthreads();

    // bitonic sort, descending (p desc, index asc on ties)
    for (unsigned k = 2u; k <= P; k <<= 1) {
        for (unsigned jj = k >> 1; jj > 0u; jj >>= 1) {
            for (unsigned i = tid; i < P; i += bd) {
                unsigned ixj = i ^ jj;
                if (ixj > i) {
                    unsigned long long a = list[i];
                    unsigned long long c = list[ixj];
                    bool up = ((i & k) == 0u);
                    bool sw = up ? (a < c) : (a > c);
                    if (sw) { list[i] = c; list[ixj] = a; }
                }
            }
            __syncthreads();
        }
    }

    if (tid < TOPK) {
        unsigned long long key = list[tid];
        float p = __uint_as_float((unsigned)(key >> 32));
        unsigned idx = 0xFFFFFFFFu - (unsigned)(key & 0xFFFFFFFFull);
        if (idx >= (unsigned)BATCHLEN) idx = 0u;   // only reachable via pad keys
        unsigned c = idx % NC;
        unsigned s = idx / NC;
        unsigned xg = s % W;
        unsigned yg = s / W;
        size_t gi = ((size_t)b * (H * W) + s) * 2;
        float dx = dxy[gi],  dy = dxy[gi + 1];
        float sw = swh[gi],  sh = swh[gi + 1];
        float xs = (float)xg + dx;
        float ysv = (float)yg + dy;
        float hw = sw * 0.5f;
        float hh = sh * 0.5f;
        const float invW = 1.0f / (float)W;
        const float invH = 1.0f / (float)H;

        int ok = b * TOPK + tid;
        out[ok * 4 + 0] = (xs - hw) * invW;
        out[ok * 4 + 1] = (ysv - hh) * invH;
        out[ok * 4 + 2] = (xs + hw) * invW;
        out[ok * 4 + 3] = (ysv + hh) * invH;
        out[BATCH * TOPK * 4 + ok] = p;                          // confi
        out[BATCH * TOPK * 4 + BATCH * TOPK + ok] = (float)c;    // classes
    }
}

extern "C" void kernel_launch(void* const* d_in, const int* in_sizes, int n_in,
                              void* d_out, int out_size) {
    const float* cls = (const float*)d_in[0];
    const float* dxy = (const float*)d_in[1];
    const float* swh = (const float*)d_in[2];
    float* out = (float*)d_out;

    zero_kernel<<<32, 1024>>>();
    peak_kernel<<<dim3(ROWLEN / 1024, H / YSTRIP, BATCH), 256>>>(cls);
    final_kernel<<<BATCH, 1024>>>(dxy, swh, out);
}